// round 3
// baseline (speedup 1.0000x reference)
#include <cuda_runtime.h>
#include <cuda_bf16.h>
#include <cub/cub.cuh>

// SegmentTarget: B=1024, N=512, W=4096
// out floats: [cls BW][delta 2BW (sline accum)][mask BW][inside BW][num_pos][num_neg]

#define TPB 256
#define EPT 16
#define MAX_B 1024
#define MAX_N 512
#define MAX_W 4096
#define MAX_BN (MAX_B*MAX_N)
#define MAX_BW (MAX_B*MAX_W)

__device__ float    g_flag[MAX_BW];        // 2.0 per sampled positive (atomicAdd)
__device__ int      g_iv[MAX_BN];
__device__ int      g_posBS[4096];
__device__ int      g_negBS[4096];
__device__ int      g_npBS[1024];          // perm-order negative block counts
__device__ int      g_scalars[4];
__device__ unsigned g_K0[MAX_BW], g_K1[MAX_BW];
__device__ unsigned g_V0[MAX_BW], g_V1[MAX_BW];
__device__ unsigned char g_cubtemp[64u << 20];
__device__ unsigned char g_pflags[MAX_BW]; // neg flag in perm order
__device__ unsigned char g_negsel[MAX_BW]; // final sampled-negative indicator

// ---------------- threefry2x32 (20 rounds), matches JAX ----------------
__host__ __device__ __forceinline__ void tf_block(unsigned k0, unsigned k1,
                                                  unsigned x0, unsigned x1,
                                                  unsigned& y0, unsigned& y1) {
    unsigned ks0 = k0, ks1 = k1, ks2 = k0 ^ k1 ^ 0x1BD11BDAu;
    x0 += ks0; x1 += ks1;
#define ROT(v,r) (((v) << (r)) | ((v) >> (32 - (r))))
#define R4(a,b,c,d) \
    x0 += x1; x1 = ROT(x1,a); x1 ^= x0; \
    x0 += x1; x1 = ROT(x1,b); x1 ^= x0; \
    x0 += x1; x1 = ROT(x1,c); x1 ^= x0; \
    x0 += x1; x1 = ROT(x1,d); x1 ^= x0;
    R4(13,15,26,6)   x0 += ks1; x1 += ks2 + 1u;
    R4(17,29,16,24)  x0 += ks2; x1 += ks0 + 2u;
    R4(13,15,26,6)   x0 += ks0; x1 += ks1 + 3u;
    R4(17,29,16,24)  x0 += ks1; x1 += ks2 + 4u;
    R4(13,15,26,6)   x0 += ks2; x1 += ks0 + 5u;
#undef R4
#undef ROT
    y0 = x0; y1 = x1;
}

// ---------------- zero output mid sections + scratch ----------------
__global__ void k_zero(float4* __restrict__ mid, int nmid4, int nflag4, int nsel4) {
    int stride = gridDim.x * blockDim.x;
    float4 z = make_float4(0.f, 0.f, 0.f, 0.f);
    uint4 zi = make_uint4(0, 0, 0, 0);
    for (int j = blockIdx.x * blockDim.x + threadIdx.x; j < nmid4; j += stride)
        mid[j] = z;
    float4* fl = (float4*)g_flag;
    for (int j = blockIdx.x * blockDim.x + threadIdx.x; j < nflag4; j += stride)
        fl[j] = z;
    uint4* ns = (uint4*)g_negsel;
    for (int j = blockIdx.x * blockDim.x + threadIdx.x; j < nsel4; j += stride)
        ns[j] = zi;
}

// ---------------- generate sort keys: partitionable random_bits ----------------
// bits[i] = y0 ^ y1 of threefry(subkey; x0 = hi64(i) = 0, x1 = i)
__global__ void k_keygen(unsigned* __restrict__ keys, unsigned* __restrict__ vals,
                         unsigned sk0, unsigned sk1, int n) {
    int i = blockIdx.x * TPB + threadIdx.x;
    if (i >= n) return;
    unsigned y0, y1;
    tf_block(sk0, sk1, 0u, (unsigned)i, y0, y1);
    keys[i] = y0 ^ y1;
    if (vals) vals[i] = (unsigned)i;
}

// ---------------- scatter mask & sline, per-block valid counts ----------------
__global__ void k_scatter(const float2* __restrict__ sp, float* __restrict__ mask,
                          float* __restrict__ sline, int BN, int N, int W) {
    int i = blockIdx.x * TPB + threadIdx.x;
    int valid = 0, ividx = 0;
    float x1 = 0.f, x2 = 0.f;
    if (i < BN) {
        float2 c = sp[i];
        x1 = c.x; x2 = c.y;
        float iv = floorf((x1 + x2) * 0.5f * 0.0625f);
        float pv = -1.0f;
        if (i % N > 0) {
            float2 p = sp[i - 1];
            pv = floorf((p.x + p.y) * 0.5f * 0.0625f);
        }
        if (iv >= 0.0f && iv != pv) {
            valid = 1;
            ividx = (int)fminf(fmaxf(iv, 0.0f), (float)(W - 1));
        }
        g_iv[i] = valid ? ividx : -1;
    }
    if (valid) {
        int cell = (i / N) * W + ividx;
        atomicAdd(mask + cell, 1.0f);
        atomicAdd(sline + 2 * cell, x1);
        atomicAdd(sline + 2 * cell + 1, x2);
    }
    __shared__ int sh[TPB];
    sh[threadIdx.x] = valid;
    __syncthreads();
    for (int off = TPB >> 1; off; off >>= 1) {
        if (threadIdx.x < off) sh[threadIdx.x] += sh[threadIdx.x + off];
        __syncthreads();
    }
    if (threadIdx.x == 0) g_posBS[blockIdx.x] = sh[0];
}

// ---------------- per-block negative-cell counts ----------------
__global__ void k_negsum(const float* __restrict__ mask, int BW) {
    int base = blockIdx.x * (TPB * EPT) + threadIdx.x * EPT;
    int cnt = 0;
#pragma unroll
    for (int j = 0; j < EPT; j += 4) {
        float4 m = *(const float4*)&mask[base + j];
        cnt += (m.x == 0.f) + (m.y == 0.f) + (m.z == 0.f) + (m.w == 0.f);
    }
    __shared__ int sh[TPB];
    sh[threadIdx.x] = cnt;
    __syncthreads();
    for (int off = TPB >> 1; off; off >>= 1) {
        if (threadIdx.x < off) sh[threadIdx.x] += sh[threadIdx.x + off];
        __syncthreads();
    }
    if (threadIdx.x == 0) g_negBS[blockIdx.x] = sh[0];
}

// ---------------- scan pos/neg block sums, emit scalars ----------------
__global__ void k_scan(float* __restrict__ out, size_t scal_off, int nPosB, int nNegB) {
    __shared__ int sh[1024];
    int t = threadIdx.x;
    int v0 = (2 * t     < nPosB) ? g_posBS[2 * t]     : 0;
    int v1 = (2 * t + 1 < nPosB) ? g_posBS[2 * t + 1] : 0;
    int s = v0 + v1;
    sh[t] = s; __syncthreads();
    for (int off = 1; off < 1024; off <<= 1) {
        int x = (t >= off) ? sh[t - off] : 0;
        __syncthreads(); sh[t] += x; __syncthreads();
    }
    int posTotal = sh[1023];
    int excl = sh[t] - s;
    __syncthreads();
    if (2 * t     < nPosB) g_posBS[2 * t]     = excl;
    if (2 * t + 1 < nPosB) g_posBS[2 * t + 1] = excl + v0;
    int v = (t < nNegB) ? g_negBS[t] : 0;
    sh[t] = v; __syncthreads();
    for (int off = 1; off < 1024; off <<= 1) {
        int x = (t >= off) ? sh[t - off] : 0;
        __syncthreads(); sh[t] += x; __syncthreads();
    }
    int negTotal = sh[1023];
    if (t < nNegB) g_negBS[t] = sh[t] - v;
    if (t == 0) {
        g_scalars[0] = posTotal;
        g_scalars[1] = negTotal;
        g_scalars[2] = min(posTotal, negTotal);
        out[scal_off]     = (float)posTotal;
        out[scal_off + 1] = (float)negTotal;
    }
}

// ---------------- sampled positives: row-major rank < ns -> flag += 2 ----------------
__global__ void k_posfin(int BN, int N, int W) {
    int i = blockIdx.x * TPB + threadIdx.x;
    int iv = (i < BN) ? g_iv[i] : -1;
    int valid = (iv >= 0);
    __shared__ int sh[TPB];
    sh[threadIdx.x] = valid;
    __syncthreads();
    for (int off = 1; off < TPB; off <<= 1) {
        int x = (threadIdx.x >= off) ? sh[threadIdx.x - off] : 0;
        __syncthreads(); sh[threadIdx.x] += x; __syncthreads();
    }
    int rank = g_posBS[blockIdx.x] + sh[threadIdx.x] - valid;
    if (valid && rank < g_scalars[2])
        atomicAdd(g_flag + (size_t)(i / N) * W + iv, 2.0f);
}

// ---------------- pass1: neg flags in perm order + block counts ----------------
__global__ void k_negflag(const unsigned* __restrict__ perm, const float* __restrict__ mask) {
    int base = blockIdx.x * (TPB * EPT) + threadIdx.x * EPT;
    union { uint4 v; unsigned char b[16]; } u;
    int cnt = 0;
#pragma unroll
    for (int j = 0; j < EPT; j++) {
        unsigned p = perm[base + j];
        unsigned char f = (mask[p] == 0.f) ? 1 : 0;
        u.b[j] = f; cnt += f;
    }
    *(uint4*)&g_pflags[base] = u.v;
    __shared__ int sh[TPB];
    sh[threadIdx.x] = cnt;
    __syncthreads();
    for (int off = TPB >> 1; off; off >>= 1) {
        if (threadIdx.x < off) sh[threadIdx.x] += sh[threadIdx.x + off];
        __syncthreads();
    }
    if (threadIdx.x == 0) g_npBS[blockIdx.x] = sh[0];
}

// ---------------- scan perm-order block counts (exclusive, in place) ----------------
__global__ void k_negscan(int n) {
    __shared__ int sh[1024];
    int t = threadIdx.x;
    int v = (t < n) ? g_npBS[t] : 0;
    sh[t] = v; __syncthreads();
    for (int off = 1; off < 1024; off <<= 1) {
        int x = (t >= off) ? sh[t - off] : 0;
        __syncthreads(); sh[t] += x; __syncthreads();
    }
    if (t < n) g_npBS[t] = sh[t] - v;
}

// ---------------- pass2: select first ns negatives in perm order ----------------
__global__ void k_negsel(const unsigned* __restrict__ perm) {
    int base = blockIdx.x * (TPB * EPT) + threadIdx.x * EPT;
    union { uint4 v; unsigned char b[16]; } u;
    u.v = *(const uint4*)&g_pflags[base];
    int cnt = 0;
#pragma unroll
    for (int j = 0; j < EPT; j++) cnt += u.b[j];
    __shared__ int sh[TPB];
    sh[threadIdx.x] = cnt;
    __syncthreads();
    for (int off = 1; off < TPB; off <<= 1) {
        int x = (threadIdx.x >= off) ? sh[threadIdx.x - off] : 0;
        __syncthreads(); sh[threadIdx.x] += x; __syncthreads();
    }
    int rank = g_npBS[blockIdx.x] + sh[threadIdx.x] - cnt;
    int ns = g_scalars[2];
    if (rank >= ns) return;  // nothing in this thread's range can be selected
#pragma unroll
    for (int j = 0; j < EPT; j++) {
        if (u.b[j]) {
            if (rank < ns) g_negsel[perm[base + j]] = 1;
            rank++;
        }
    }
}

// ---------------- epilogue ----------------
__global__ void k_final(float* __restrict__ out, int BW, int W) {
    const float* mask = out + (size_t)3 * BW;
    float* delta  = out + (size_t)BW;
    float* cls    = out;
    float* inside = out + (size_t)4 * BW;

    int tbase = blockIdx.x * (TPB * EPT) + threadIdx.x * EPT;
    union { uint4 v; unsigned char b[16]; } ns;
    ns.v = *(const uint4*)&g_negsel[tbase];

#pragma unroll
    for (int j = 0; j < EPT; j += 4) {
        int i0 = tbase + j;
        float4 m  = *(const float4*)&mask[i0];
        float4 fl = *(const float4*)&g_flag[i0];
        float marr[4]  = {m.x, m.y, m.z, m.w};
        float flarr[4] = {fl.x, fl.y, fl.z, fl.w};
        float clsarr[4], insarr[4];
#pragma unroll
        for (int q = 0; q < 4; q++) {
            bool neg = (marr[q] == 0.0f);
            float flag = flarr[q] + (float)ns.b[j + q];
            insarr[q] = (flag == 2.0f) ? 2.0f : ((flag == 1.0f) ? 1.0f : 0.0f);
            clsarr[q] = neg ? 0.1f : 0.9f;
        }
        *(float4*)&cls[i0]    = make_float4(clsarr[0], clsarr[1], clsarr[2], clsarr[3]);
        *(float4*)&inside[i0] = make_float4(insarr[0], insarr[1], insarr[2], insarr[3]);

        float4 d0 = *(float4*)&delta[2 * (size_t)i0];
        float4 d1 = *(float4*)&delta[2 * (size_t)i0 + 4];
        float c0 = (float)((i0)     % W) + 0.5f;
        float c1 = (float)((i0 + 1) % W) + 0.5f;
        float c2 = (float)((i0 + 2) % W) + 0.5f;
        float c3 = (float)((i0 + 3) % W) + 0.5f;
        d0.x = d0.x * 0.0625f - c0;  d0.y = d0.y * 0.0625f - c0;
        d0.z = d0.z * 0.0625f - c1;  d0.w = d0.w * 0.0625f - c1;
        d1.x = d1.x * 0.0625f - c2;  d1.y = d1.y * 0.0625f - c2;
        d1.z = d1.z * 0.0625f - c3;  d1.w = d1.w * 0.0625f - c3;
        *(float4*)&delta[2 * (size_t)i0]     = d0;
        *(float4*)&delta[2 * (size_t)i0 + 4] = d1;
    }
}

extern "C" void kernel_launch(void* const* d_in, const int* in_sizes, int n_in,
                              void* d_out, int out_size) {
    const float* sp = (const float*)d_in[0];
    int B = in_sizes[2];
    int W = in_sizes[1] / B;
    int N = in_sizes[0] / (2 * B);
    int BN = B * N;
    int BW = B * W;

    float* out   = (float*)d_out;
    float* mask  = out + (size_t)3 * BW;
    float* sline = out + (size_t)BW;

    // --- host threefry key chain (partitionable, modern JAX default) ---
    // split(key): keys[j] = (y0, y1) of block(key; 0, j). key=keys[0], subkey=keys[1].
    unsigned k10, k11, s10, s11, k20, k21, s20, s21, k30, k31, s30, s31;
    tf_block(0u, 42u, 0u, 0u, k10, k11);   // key1
    tf_block(0u, 42u, 0u, 1u, s10, s11);   // subkey1
    tf_block(k10, k11, 0u, 0u, k20, k21);  // key2
    tf_block(k10, k11, 0u, 1u, s20, s21);  // subkey2
    tf_block(k20, k21, 0u, 0u, k30, k31);  // key3 (unused)
    tf_block(k20, k21, 0u, 1u, s30, s31);  // subkey3

    unsigned *K0, *K1, *V0, *V1;
    void* tmp;
    cudaGetSymbolAddress((void**)&K0, g_K0);
    cudaGetSymbolAddress((void**)&K1, g_K1);
    cudaGetSymbolAddress((void**)&V0, g_V0);
    cudaGetSymbolAddress((void**)&V1, g_V1);
    cudaGetSymbolAddress(&tmp, g_cubtemp);

    // zero output mid sections + flag + negsel
    k_zero<<<2048, TPB>>>((float4*)(out + (size_t)BW), (3 * BW) / 4, BW / 4, BW / 16);

    // mask / scatter pipeline
    int nPosB = (BN + TPB - 1) / TPB;
    k_scatter<<<nPosB, TPB>>>((const float2*)sp, mask, sline, BN, N, W);
    int nNegB = (BW + TPB * EPT - 1) / (TPB * EPT);
    k_negsum<<<nNegB, TPB>>>(mask, BW);
    k_scan<<<1, 1024>>>(out, (size_t)5 * BW, nPosB, nNegB);
    k_posfin<<<nPosB, TPB>>>(BN, N, W);

    // --- exact JAX permutation: 3 rounds of keygen + stable radix sort ---
    cub::DoubleBuffer<unsigned> dK(K0, K1);
    cub::DoubleBuffer<unsigned> dV(V0, V1);
    size_t tb = 0;
    cub::DeviceRadixSort::SortPairs(nullptr, tb, dK, dV, BW);  // size query only

    int kgB = (BW + TPB - 1) / TPB;
    k_keygen<<<kgB, TPB>>>(dK.Current(), dV.Current(), s10, s11, BW);
    cub::DeviceRadixSort::SortPairs(tmp, tb, dK, dV, BW);
    k_keygen<<<kgB, TPB>>>(dK.Current(), nullptr, s20, s21, BW);
    cub::DeviceRadixSort::SortPairs(tmp, tb, dK, dV, BW);
    k_keygen<<<kgB, TPB>>>(dK.Current(), nullptr, s30, s31, BW);
    cub::DeviceRadixSort::SortPairs(tmp, tb, dK, dV, BW);
    const unsigned* perm = dV.Current();

    // --- negative sampling in perm order ---
    k_negflag<<<nNegB, TPB>>>(perm, mask);
    k_negscan<<<1, 1024>>>(nNegB);
    k_negsel<<<nNegB, TPB>>>(perm);

    // --- epilogue ---
    k_final<<<nNegB, TPB>>>(out, BW, W);
}

// round 4
// speedup vs baseline: 1.1925x; 1.1925x over previous
#include <cuda_runtime.h>
#include <cuda_bf16.h>
#include <cub/cub.cuh>

// SegmentTarget: B=1024, N=512, W=4096
// out floats: [cls BW][delta 2BW (sline accum)][mask BW][inside BW][num_pos][num_neg]

#define TPB 256
#define EPT 16
#define MAX_B 1024
#define MAX_N 512
#define MAX_W 4096
#define MAX_BN (MAX_B*MAX_N)
#define MAX_BW (MAX_B*MAX_W)

// round-3 prefix threshold: keep q with key3(q) <= K3 (0.16 * 2^32).
// Guarantees (>80 sigma) the compacted prefix holds >= ns negatives.
#define K3_THRESH 687194767u
#define CMAX 720896               // 704 * 1024, |S| ~ 671K +- 0.75K
#define EPT_S 4

__device__ float    g_flag[MAX_BW];        // 2.0 per sampled positive
__device__ int      g_iv[MAX_BN];
__device__ int      g_posBS[4096];
__device__ int      g_negBS[4096];
__device__ int      g_npBS[1024];          // passA block counts
__device__ int      g_npBS2[1024];         // small-phase block counts
__device__ int      g_scalars[4];
__device__ unsigned g_K0[MAX_BW], g_K1[MAX_BW];
__device__ unsigned g_V0[MAX_BW], g_V1[MAX_BW];
__device__ unsigned g_SK0[CMAX], g_SK1[CMAX];
__device__ unsigned g_SV0[CMAX], g_SV1[CMAX];
__device__ unsigned g_SE[CMAX];            // element id per sorted-prefix slot
__device__ unsigned char g_SF[CMAX];       // negativity flag per slot
__device__ unsigned char g_cubtemp[64u << 20];
__device__ unsigned char g_negsel[MAX_BW];

// ---------------- threefry2x32 (20 rounds), matches JAX ----------------
__host__ __device__ __forceinline__ void tf_block(unsigned k0, unsigned k1,
                                                  unsigned x0, unsigned x1,
                                                  unsigned& y0, unsigned& y1) {
    unsigned ks0 = k0, ks1 = k1, ks2 = k0 ^ k1 ^ 0x1BD11BDAu;
    x0 += ks0; x1 += ks1;
#define ROT(v,r) (((v) << (r)) | ((v) >> (32 - (r))))
#define R4(a,b,c,d) \
    x0 += x1; x1 = ROT(x1,a); x1 ^= x0; \
    x0 += x1; x1 = ROT(x1,b); x1 ^= x0; \
    x0 += x1; x1 = ROT(x1,c); x1 ^= x0; \
    x0 += x1; x1 = ROT(x1,d); x1 ^= x0;
    R4(13,15,26,6)   x0 += ks1; x1 += ks2 + 1u;
    R4(17,29,16,24)  x0 += ks2; x1 += ks0 + 2u;
    R4(13,15,26,6)   x0 += ks0; x1 += ks1 + 3u;
    R4(17,29,16,24)  x0 += ks1; x1 += ks2 + 4u;
    R4(13,15,26,6)   x0 += ks2; x1 += ks0 + 5u;
#undef R4
#undef ROT
    y0 = x0; y1 = x1;
}

__device__ __forceinline__ unsigned tf_bits(unsigned k0, unsigned k1, unsigned i) {
    unsigned y0, y1;
    tf_block(k0, k1, 0u, i, y0, y1);
    return y0 ^ y1;   // partitionable random_bits: xor of the pair
}

// ---------------- zero output mid sections + scratch ----------------
__global__ void k_zero(float4* __restrict__ mid, int nmid4, int nflag4, int nsel4) {
    int stride = gridDim.x * blockDim.x;
    float4 z = make_float4(0.f, 0.f, 0.f, 0.f);
    uint4 zi = make_uint4(0, 0, 0, 0);
    for (int j = blockIdx.x * blockDim.x + threadIdx.x; j < nmid4; j += stride)
        mid[j] = z;
    float4* fl = (float4*)g_flag;
    for (int j = blockIdx.x * blockDim.x + threadIdx.x; j < nflag4; j += stride)
        fl[j] = z;
    uint4* ns = (uint4*)g_negsel;
    for (int j = blockIdx.x * blockDim.x + threadIdx.x; j < nsel4; j += stride)
        ns[j] = zi;
}

// ---------------- generate sort keys (rounds 1 & 2) ----------------
__global__ void k_keygen(unsigned* __restrict__ keys, unsigned* __restrict__ vals,
                         unsigned sk0, unsigned sk1, int n) {
    int i = blockIdx.x * TPB + threadIdx.x;
    if (i >= n) return;
    keys[i] = tf_bits(sk0, sk1, (unsigned)i);
    if (vals) vals[i] = (unsigned)i;
}

// ---------------- scatter mask & sline, per-block valid counts ----------------
__global__ void k_scatter(const float2* __restrict__ sp, float* __restrict__ mask,
                          float* __restrict__ sline, int BN, int N, int W) {
    int i = blockIdx.x * TPB + threadIdx.x;
    int valid = 0, ividx = 0;
    float x1 = 0.f, x2 = 0.f;
    if (i < BN) {
        float2 c = sp[i];
        x1 = c.x; x2 = c.y;
        float iv = floorf((x1 + x2) * 0.5f * 0.0625f);
        float pv = -1.0f;
        if (i % N > 0) {
            float2 p = sp[i - 1];
            pv = floorf((p.x + p.y) * 0.5f * 0.0625f);
        }
        if (iv >= 0.0f && iv != pv) {
            valid = 1;
            ividx = (int)fminf(fmaxf(iv, 0.0f), (float)(W - 1));
        }
        g_iv[i] = valid ? ividx : -1;
    }
    if (valid) {
        int cell = (i / N) * W + ividx;
        atomicAdd(mask + cell, 1.0f);
        atomicAdd(sline + 2 * cell, x1);
        atomicAdd(sline + 2 * cell + 1, x2);
    }
    __shared__ int sh[TPB];
    sh[threadIdx.x] = valid;
    __syncthreads();
    for (int off = TPB >> 1; off; off >>= 1) {
        if (threadIdx.x < off) sh[threadIdx.x] += sh[threadIdx.x + off];
        __syncthreads();
    }
    if (threadIdx.x == 0) g_posBS[blockIdx.x] = sh[0];
}

// ---------------- per-block negative-cell counts ----------------
__global__ void k_negsum(const float* __restrict__ mask, int BW) {
    int base = blockIdx.x * (TPB * EPT) + threadIdx.x * EPT;
    int cnt = 0;
#pragma unroll
    for (int j = 0; j < EPT; j += 4) {
        float4 m = *(const float4*)&mask[base + j];
        cnt += (m.x == 0.f) + (m.y == 0.f) + (m.z == 0.f) + (m.w == 0.f);
    }
    __shared__ int sh[TPB];
    sh[threadIdx.x] = cnt;
    __syncthreads();
    for (int off = TPB >> 1; off; off >>= 1) {
        if (threadIdx.x < off) sh[threadIdx.x] += sh[threadIdx.x + off];
        __syncthreads();
    }
    if (threadIdx.x == 0) g_negBS[blockIdx.x] = sh[0];
}

// ---------------- scan pos/neg block sums, emit scalars ----------------
__global__ void k_scan(float* __restrict__ out, size_t scal_off, int nPosB, int nNegB) {
    __shared__ int sh[1024];
    int t = threadIdx.x;
    int v0 = (2 * t     < nPosB) ? g_posBS[2 * t]     : 0;
    int v1 = (2 * t + 1 < nPosB) ? g_posBS[2 * t + 1] : 0;
    int s = v0 + v1;
    sh[t] = s; __syncthreads();
    for (int off = 1; off < 1024; off <<= 1) {
        int x = (t >= off) ? sh[t - off] : 0;
        __syncthreads(); sh[t] += x; __syncthreads();
    }
    int posTotal = sh[1023];
    int excl = sh[t] - s;
    __syncthreads();
    if (2 * t     < nPosB) g_posBS[2 * t]     = excl;
    if (2 * t + 1 < nPosB) g_posBS[2 * t + 1] = excl + v0;
    int v = (t < nNegB) ? g_negBS[t] : 0;
    sh[t] = v; __syncthreads();
    for (int off = 1; off < 1024; off <<= 1) {
        int x = (t >= off) ? sh[t - off] : 0;
        __syncthreads(); sh[t] += x; __syncthreads();
    }
    int negTotal = sh[1023];
    if (t < nNegB) g_negBS[t] = sh[t] - v;
    if (t == 0) {
        g_scalars[0] = posTotal;
        g_scalars[1] = negTotal;
        g_scalars[2] = min(posTotal, negTotal);
        out[scal_off]     = (float)posTotal;
        out[scal_off + 1] = (float)negTotal;
    }
}

// ---------------- sampled positives: row-major rank < ns -> flag += 2 ----------------
__global__ void k_posfin(int BN, int N, int W) {
    int i = blockIdx.x * TPB + threadIdx.x;
    int iv = (i < BN) ? g_iv[i] : -1;
    int valid = (iv >= 0);
    __shared__ int sh[TPB];
    sh[threadIdx.x] = valid;
    __syncthreads();
    for (int off = 1; off < TPB; off <<= 1) {
        int x = (threadIdx.x >= off) ? sh[threadIdx.x - off] : 0;
        __syncthreads(); sh[threadIdx.x] += x; __syncthreads();
    }
    int rank = g_posBS[blockIdx.x] + sh[threadIdx.x] - valid;
    if (valid && rank < g_scalars[2])
        atomicAdd(g_flag + (size_t)(i / N) * W + iv, 2.0f);
}

// ---------------- generic 1-block exclusive scan over blocksum array ----------------
__global__ void k_bscan(int* __restrict__ arr, int n) {
    __shared__ int sh[1024];
    int t = threadIdx.x;
    int v = (t < n) ? arr[t] : 0;
    sh[t] = v; __syncthreads();
    for (int off = 1; off < 1024; off <<= 1) {
        int x = (t >= off) ? sh[t - off] : 0;
        __syncthreads(); sh[t] += x; __syncthreads();
    }
    if (t < n) arr[t] = sh[t] - v;
}

// ---------------- round 3, passA: count key3(q) <= K3 per block ----------------
__global__ void k_passA(unsigned sk0, unsigned sk1) {
    int base = blockIdx.x * (TPB * EPT) + threadIdx.x * EPT;
    int cnt = 0;
#pragma unroll
    for (int j = 0; j < EPT; j++)
        cnt += (tf_bits(sk0, sk1, (unsigned)(base + j)) <= K3_THRESH);
    __shared__ int sh[TPB];
    sh[threadIdx.x] = cnt;
    __syncthreads();
    for (int off = TPB >> 1; off; off >>= 1) {
        if (threadIdx.x < off) sh[threadIdx.x] += sh[threadIdx.x + off];
        __syncthreads();
    }
    if (threadIdx.x == 0) g_npBS[blockIdx.x] = sh[0];
}

// ---------------- fill small sort input with sentinels ----------------
__global__ void k_fill(unsigned* __restrict__ sk, unsigned* __restrict__ sv) {
    int j = blockIdx.x * TPB + threadIdx.x;
    uint4 s = make_uint4(0xFFFFFFFFu, 0xFFFFFFFFu, 0xFFFFFFFFu, 0xFFFFFFFFu);
    uint4 z = make_uint4(0, 0, 0, 0);
    ((uint4*)sk)[j] = s;
    ((uint4*)sv)[j] = z;
}

// ---------------- round 3, passB: order-preserving compaction ----------------
__global__ void k_passB(unsigned sk0, unsigned sk1,
                        unsigned* __restrict__ sk, unsigned* __restrict__ sv) {
    int base = blockIdx.x * (TPB * EPT) + threadIdx.x * EPT;
    unsigned keys[EPT];
    int cnt = 0;
#pragma unroll
    for (int j = 0; j < EPT; j++) {
        keys[j] = tf_bits(sk0, sk1, (unsigned)(base + j));
        cnt += (keys[j] <= K3_THRESH);
    }
    __shared__ int sh[TPB];
    sh[threadIdx.x] = cnt;
    __syncthreads();
    for (int off = 1; off < TPB; off <<= 1) {
        int x = (threadIdx.x >= off) ? sh[threadIdx.x - off] : 0;
        __syncthreads(); sh[threadIdx.x] += x; __syncthreads();
    }
    int pos = g_npBS[blockIdx.x] + sh[threadIdx.x] - cnt;
#pragma unroll
    for (int j = 0; j < EPT; j++) {
        if (keys[j] <= K3_THRESH) {
            if (pos < CMAX) { sk[pos] = keys[j]; sv[pos] = (unsigned)(base + j); }
            pos++;
        }
    }
}

// ---------------- small phase 1: gather element + negativity, block counts ----------------
__global__ void k_smallGather(const unsigned* __restrict__ sk, const unsigned* __restrict__ sv,
                              const unsigned* __restrict__ perm2, const float* __restrict__ mask) {
    int base = blockIdx.x * (TPB * EPT_S) + threadIdx.x * EPT_S;
    int cnt = 0;
    unsigned es[EPT_S];
    unsigned char fs[EPT_S];
#pragma unroll
    for (int j = 0; j < EPT_S; j++) {
        unsigned key = sk[base + j];
        unsigned q = sv[base + j];
        unsigned e = 0;
        unsigned char f = 0;
        if (key != 0xFFFFFFFFu) {
            e = perm2[q];
            f = (mask[e] == 0.f) ? 1 : 0;
        }
        es[j] = e; fs[j] = f; cnt += f;
    }
#pragma unroll
    for (int j = 0; j < EPT_S; j++) g_SE[base + j] = es[j];
    *(uchar4*)&g_SF[base] = make_uchar4(fs[0], fs[1], fs[2], fs[3]);
    __shared__ int sh[TPB];
    sh[threadIdx.x] = cnt;
    __syncthreads();
    for (int off = TPB >> 1; off; off >>= 1) {
        if (threadIdx.x < off) sh[threadIdx.x] += sh[threadIdx.x + off];
        __syncthreads();
    }
    if (threadIdx.x == 0) g_npBS2[blockIdx.x] = sh[0];
}

// ---------------- small phase 2: select first ns negatives ----------------
__global__ void k_smallSel() {
    int base = blockIdx.x * (TPB * EPT_S) + threadIdx.x * EPT_S;
    uchar4 f4 = *(const uchar4*)&g_SF[base];
    unsigned char fs[EPT_S] = {f4.x, f4.y, f4.z, f4.w};
    int cnt = fs[0] + fs[1] + fs[2] + fs[3];
    __shared__ int sh[TPB];
    sh[threadIdx.x] = cnt;
    __syncthreads();
    for (int off = 1; off < TPB; off <<= 1) {
        int x = (threadIdx.x >= off) ? sh[threadIdx.x - off] : 0;
        __syncthreads(); sh[threadIdx.x] += x; __syncthreads();
    }
    int rank = g_npBS2[blockIdx.x] + sh[threadIdx.x] - cnt;
    int ns = g_scalars[2];
    if (rank >= ns) return;
#pragma unroll
    for (int j = 0; j < EPT_S; j++) {
        if (fs[j]) {
            if (rank < ns) g_negsel[g_SE[base + j]] = 1;
            rank++;
        }
    }
}

// ---------------- epilogue ----------------
__global__ void k_final(float* __restrict__ out, int BW, int W) {
    const float* mask = out + (size_t)3 * BW;
    float* delta  = out + (size_t)BW;
    float* cls    = out;
    float* inside = out + (size_t)4 * BW;

    int tbase = blockIdx.x * (TPB * EPT) + threadIdx.x * EPT;
    union { uint4 v; unsigned char b[16]; } ns;
    ns.v = *(const uint4*)&g_negsel[tbase];

#pragma unroll
    for (int j = 0; j < EPT; j += 4) {
        int i0 = tbase + j;
        float4 m  = *(const float4*)&mask[i0];
        float4 fl = *(const float4*)&g_flag[i0];
        float marr[4]  = {m.x, m.y, m.z, m.w};
        float flarr[4] = {fl.x, fl.y, fl.z, fl.w};
        float clsarr[4], insarr[4];
#pragma unroll
        for (int q = 0; q < 4; q++) {
            bool neg = (marr[q] == 0.0f);
            float flag = flarr[q] + (float)ns.b[j + q];
            insarr[q] = (flag == 2.0f) ? 2.0f : ((flag == 1.0f) ? 1.0f : 0.0f);
            clsarr[q] = neg ? 0.1f : 0.9f;
        }
        *(float4*)&cls[i0]    = make_float4(clsarr[0], clsarr[1], clsarr[2], clsarr[3]);
        *(float4*)&inside[i0] = make_float4(insarr[0], insarr[1], insarr[2], insarr[3]);

        float4 d0 = *(float4*)&delta[2 * (size_t)i0];
        float4 d1 = *(float4*)&delta[2 * (size_t)i0 + 4];
        float c0 = (float)((i0)     % W) + 0.5f;
        float c1 = (float)((i0 + 1) % W) + 0.5f;
        float c2 = (float)((i0 + 2) % W) + 0.5f;
        float c3 = (float)((i0 + 3) % W) + 0.5f;
        d0.x = d0.x * 0.0625f - c0;  d0.y = d0.y * 0.0625f - c0;
        d0.z = d0.z * 0.0625f - c1;  d0.w = d0.w * 0.0625f - c1;
        d1.x = d1.x * 0.0625f - c2;  d1.y = d1.y * 0.0625f - c2;
        d1.z = d1.z * 0.0625f - c3;  d1.w = d1.w * 0.0625f - c3;
        *(float4*)&delta[2 * (size_t)i0]     = d0;
        *(float4*)&delta[2 * (size_t)i0 + 4] = d1;
    }
}

extern "C" void kernel_launch(void* const* d_in, const int* in_sizes, int n_in,
                              void* d_out, int out_size) {
    const float* sp = (const float*)d_in[0];
    int B = in_sizes[2];
    int W = in_sizes[1] / B;
    int N = in_sizes[0] / (2 * B);
    int BN = B * N;
    int BW = B * W;

    float* out   = (float*)d_out;
    float* mask  = out + (size_t)3 * BW;
    float* sline = out + (size_t)BW;

    // --- host threefry key chain (partitionable, modern JAX default) ---
    unsigned k10, k11, s10, s11, k20, k21, s20, s21, k30, k31, s30, s31;
    tf_block(0u, 42u, 0u, 0u, k10, k11);
    tf_block(0u, 42u, 0u, 1u, s10, s11);
    tf_block(k10, k11, 0u, 0u, k20, k21);
    tf_block(k10, k11, 0u, 1u, s20, s21);
    tf_block(k20, k21, 0u, 0u, k30, k31);
    tf_block(k20, k21, 0u, 1u, s30, s31);

    unsigned *K0, *K1, *V0, *V1, *SK0, *SK1, *SV0, *SV1;
    void* tmp;
    cudaGetSymbolAddress((void**)&K0, g_K0);
    cudaGetSymbolAddress((void**)&K1, g_K1);
    cudaGetSymbolAddress((void**)&V0, g_V0);
    cudaGetSymbolAddress((void**)&V1, g_V1);
    cudaGetSymbolAddress((void**)&SK0, g_SK0);
    cudaGetSymbolAddress((void**)&SK1, g_SK1);
    cudaGetSymbolAddress((void**)&SV0, g_SV0);
    cudaGetSymbolAddress((void**)&SV1, g_SV1);
    cudaGetSymbolAddress(&tmp, g_cubtemp);

    k_zero<<<2048, TPB>>>((float4*)(out + (size_t)BW), (3 * BW) / 4, BW / 4, BW / 16);

    int nPosB = (BN + TPB - 1) / TPB;
    k_scatter<<<nPosB, TPB>>>((const float2*)sp, mask, sline, BN, N, W);
    int nNegB = (BW + TPB * EPT - 1) / (TPB * EPT);
    k_negsum<<<nNegB, TPB>>>(mask, BW);
    k_scan<<<1, 1024>>>(out, (size_t)5 * BW, nPosB, nNegB);
    k_posfin<<<nPosB, TPB>>>(BN, N, W);

    // --- rounds 1 & 2: full stable pair sorts ---
    cub::DoubleBuffer<unsigned> dK(K0, K1);
    cub::DoubleBuffer<unsigned> dV(V0, V1);
    size_t tb = 0;
    cub::DeviceRadixSort::SortPairs(nullptr, tb, dK, dV, BW);

    int kgB = (BW + TPB - 1) / TPB;
    k_keygen<<<kgB, TPB>>>(dK.Current(), dV.Current(), s10, s11, BW);
    cub::DeviceRadixSort::SortPairs(tmp, tb, dK, dV, BW);
    k_keygen<<<kgB, TPB>>>(dK.Current(), nullptr, s20, s21, BW);
    cub::DeviceRadixSort::SortPairs(tmp, tb, dK, dV, BW);
    const unsigned* perm2 = dV.Current();

    // --- round 3: prefix-threshold compaction + small fixed-size sort ---
    k_passA<<<nNegB, TPB>>>(s30, s31);
    k_bscan<<<1, 1024>>>((int*)0 + 0, 0);  // placeholder removed below
    // (real scan)
    {
        int* npBS;
        cudaGetSymbolAddress((void**)&npBS, g_npBS);
        k_bscan<<<1, 1024>>>(npBS, nNegB);
    }
    k_fill<<<CMAX / (TPB * 4), TPB>>>(SK0, SV0);
    k_passB<<<nNegB, TPB>>>(s30, s31, SK0, SV0);

    cub::DoubleBuffer<unsigned> dSK(SK0, SK1);
    cub::DoubleBuffer<unsigned> dSV(SV0, SV1);
    size_t tb2 = 0;
    cub::DeviceRadixSort::SortPairs(nullptr, tb2, dSK, dSV, CMAX);
    cub::DeviceRadixSort::SortPairs(tmp, tb2, dSK, dSV, CMAX);

    int nSmallB = CMAX / (TPB * EPT_S);
    k_smallGather<<<nSmallB, TPB>>>(dSK.Current(), dSV.Current(), perm2, mask);
    {
        int* npBS2;
        cudaGetSymbolAddress((void**)&npBS2, g_npBS2);
        k_bscan<<<1, 1024>>>(npBS2, nSmallB);
    }
    k_smallSel<<<nSmallB, TPB>>>();

    k_final<<<nNegB, TPB>>>(out, BW, W);
}